// round 1
// baseline (speedup 1.0000x reference)
#include <cuda_runtime.h>
#include <math.h>

#define BB 8
#define NN 2048
#define DD 128
#define TWO_PI_F 6.283185307179586f

// Static device scratch (no allocations allowed).
__device__ float d_C[(size_t)BB * NN * NN];      // 134 MB coupling matrix
__device__ float d_theta_buf[2 * BB * NN];       // ping-pong theta

// coupling = clip(exp(-acosh(max(-lz,1+1e-7)) / (1+1e-6)), 0, 1)
//          ≈ x - sqrt(x^2 - 1),  x = max(-lz, 1+1e-7)   (error ~5e-6, see analysis)
// sqrt via FMA-pipe Newton (avoid MUFU bottleneck: rt_SMSP=8 would cost ~500us chip-wide)
__device__ __forceinline__ float coupling_from_lz(float lz) {
    float x = fmaxf(-lz, 1.0f + 1e-7f);
    float t = (x - 1.0f) * (x + 1.0f);          // x^2-1, cancellation-free near 1
    float xh = 0.5f * t;
    float r = __int_as_float(0x5f375a86 - (__float_as_int(t) >> 1));
    r = r * (1.5f - xh * r * r);
    r = r * (1.5f - xh * r * r);
    r = r * (1.5f - xh * r * r);
    float s = t * r;                             // sqrt(t)
    float c = x - s;
    return fminf(fmaxf(c, 0.0f), 1.0f);
}

#define BM 64
#define BN 64
#define BK 32

// Build C[b,n,m]: tiled "Lorentz GEMM" (component 0 of A negated), fp32.
__global__ void build_coupling_kernel(const float* __restrict__ emb) {
    int b  = blockIdx.z;
    int n0 = blockIdx.y * BM;
    int m0 = blockIdx.x * BN;
    const float* E = emb + (size_t)b * NN * DD;

    __shared__ float As[BK][BM];
    __shared__ float Bs[BK][BN];

    int tx = threadIdx.x, ty = threadIdx.y;          // block (16,16)
    int tid = ty * 16 + tx;
    int loadRow = tid >> 3;                          // 0..31
    int loadK   = (tid & 7) * 4;                     // 0,4,...,28

    float acc[4][4] = {};

    for (int k0 = 0; k0 < DD; k0 += BK) {
        #pragma unroll
        for (int rr = 0; rr < 2; rr++) {
            int row = loadRow + rr * 32;
            float4 v = *(const float4*)(E + (size_t)(n0 + row) * DD + k0 + loadK);
            if (k0 == 0 && loadK == 0) v.x = -v.x;   // negate time component on A side
            As[loadK + 0][row] = v.x;
            As[loadK + 1][row] = v.y;
            As[loadK + 2][row] = v.z;
            As[loadK + 3][row] = v.w;
            float4 w = *(const float4*)(E + (size_t)(m0 + row) * DD + k0 + loadK);
            Bs[loadK + 0][row] = w.x;
            Bs[loadK + 1][row] = w.y;
            Bs[loadK + 2][row] = w.z;
            Bs[loadK + 3][row] = w.w;
        }
        __syncthreads();

        #pragma unroll
        for (int kk = 0; kk < BK; kk++) {
            float4 a4 = *(const float4*)&As[kk][ty * 4];
            float4 b4 = *(const float4*)&Bs[kk][tx * 4];
            float a[4] = {a4.x, a4.y, a4.z, a4.w};
            float bv[4] = {b4.x, b4.y, b4.z, b4.w};
            #pragma unroll
            for (int i = 0; i < 4; i++)
                #pragma unroll
                for (int j = 0; j < 4; j++)
                    acc[i][j] = fmaf(a[i], bv[j], acc[i][j]);
        }
        __syncthreads();
    }

    // Epilogue: lorentz -> coupling, vectorized store
    #pragma unroll
    for (int i = 0; i < 4; i++) {
        int n = n0 + ty * 4 + i;
        float4 o;
        o.x = coupling_from_lz(acc[i][0]);
        o.y = coupling_from_lz(acc[i][1]);
        o.z = coupling_from_lz(acc[i][2]);
        o.w = coupling_from_lz(acc[i][3]);
        *(float4*)(d_C + ((size_t)b * NN + n) * NN + m0 + tx * 4) = o;
    }
}

// One Kuramoto step. Block = 512 threads (16 warps) handles 16 rows of one batch.
// sin(th_n - th_m) decomposed: csum = sin_n * (C·cos) - cos_n * (C·sin)
__global__ void step_kernel(const float* __restrict__ src,
                            float* __restrict__ dst,
                            const float* __restrict__ omega) {
    __shared__ float cs[NN];
    __shared__ float sn[NN];

    int b = blockIdx.y;
    const float* th_b = src + b * NN;

    for (int i = threadIdx.x; i < NN; i += blockDim.x) {
        float s, c;
        sincosf(th_b[i], &s, &c);
        cs[i] = c;
        sn[i] = s;
    }
    __syncthreads();

    int wid  = threadIdx.x >> 5;
    int lane = threadIdx.x & 31;
    int n = blockIdx.x * 16 + wid;

    const float4* Crow = (const float4*)(d_C + ((size_t)b * NN + n) * NN);
    const float4* cs4 = (const float4*)cs;
    const float4* sn4 = (const float4*)sn;

    float sum_c = 0.0f, sum_s = 0.0f;
    #pragma unroll
    for (int it = 0; it < NN / (32 * 4); it++) {
        int j4 = it * 32 + lane;
        float4 cv = Crow[j4];
        float4 cc = cs4[j4];
        float4 ss = sn4[j4];
        sum_c = fmaf(cv.x, cc.x, sum_c);
        sum_c = fmaf(cv.y, cc.y, sum_c);
        sum_c = fmaf(cv.z, cc.z, sum_c);
        sum_c = fmaf(cv.w, cc.w, sum_c);
        sum_s = fmaf(cv.x, ss.x, sum_s);
        sum_s = fmaf(cv.y, ss.y, sum_s);
        sum_s = fmaf(cv.z, ss.z, sum_s);
        sum_s = fmaf(cv.w, ss.w, sum_s);
    }

    #pragma unroll
    for (int off = 16; off > 0; off >>= 1) {
        sum_c += __shfl_xor_sync(0xFFFFFFFFu, sum_c, off);
        sum_s += __shfl_xor_sync(0xFFFFFFFFu, sum_s, off);
    }

    if (lane == 0) {
        float th = th_b[n];
        float csum = sn[n] * sum_c - cs[n] * sum_s;
        float dth = omega[n] + (1.0f / NN) * csum;   // K_STRENGTH/N
        dst[b * NN + n] = fmodf(th + 0.1f * dth, TWO_PI_F);
    }
}

extern "C" void kernel_launch(void* const* d_in, const int* in_sizes, int n_in,
                              void* d_out, int out_size) {
    const float* initial = (const float*)d_in[0];   // (B,N)
    const float* emb     = (const float*)d_in[1];   // (B,N,D)
    const float* omega   = (const float*)d_in[2];   // (N,)
    float* out = (float*)d_out;                     // (B,N)

    float* buf = nullptr;
    cudaGetSymbolAddress((void**)&buf, d_theta_buf);

    dim3 bgrid(NN / BN, NN / BM, BB);
    dim3 bblock(16, 16);
    build_coupling_kernel<<<bgrid, bblock>>>(emb);

    dim3 sgrid(NN / 16, BB);
    for (int k = 0; k < 16; k++) {
        const float* src = (k == 0)  ? initial : buf + ((k + 1) & 1) * BB * NN;
        float*       dst = (k == 15) ? out     : buf + (k & 1) * BB * NN;
        step_kernel<<<sgrid, 512>>>(src, dst, omega);
    }
}

// round 2
// speedup vs baseline: 1.5224x; 1.5224x over previous
#include <cuda_runtime.h>
#include <cuda_fp16.h>
#include <math.h>

#define BB 8
#define NN 2048
#define DD 128
#define TWO_PI_F 6.283185307179586f

// Static device scratch (no allocations allowed).
__device__ __half d_C[(size_t)BB * NN * NN];   // 67 MB coupling matrix (fp16, L2-resident)
__device__ float d_theta_buf[2 * BB * NN];     // ping-pong theta

// ---- packed f32x2 helpers (Blackwell FFMA2: 2x fp32 FMA per instruction) ----
static __device__ __forceinline__ unsigned long long pack2(float lo, float hi) {
    unsigned long long r;
    asm("mov.b64 %0, {%1, %2};" : "=l"(r) : "f"(lo), "f"(hi));
    return r;
}
static __device__ __forceinline__ void unpack2(unsigned long long v, float& lo, float& hi) {
    asm("mov.b64 {%0, %1}, %2;" : "=f"(lo), "=f"(hi) : "l"(v));
}
static __device__ __forceinline__ void fma2(unsigned long long& d,
                                            unsigned long long a,
                                            unsigned long long b) {
    asm("fma.rn.f32x2 %0, %1, %2, %0;" : "+l"(d) : "l"(a), "l"(b));
}

// coupling = clip(exp(-acosh(max(-lz,1+1e-7)) / (1+1e-6)), 0, 1)
//          ≈ x - sqrt(x^2-1),  x = max(-lz, 1+1e-7)   (exact identity up to exp(1e-6*d) ≤ 1+5e-6)
// sqrt via FMA-pipe Newton (MUFU at rt=8/SMSP would cost ~500us chip-wide for 33.5M^3 ops)
__device__ __forceinline__ float coupling_from_lz(float lz) {
    float x = fmaxf(-lz, 1.0f + 1e-7f);
    float t = (x - 1.0f) * (x + 1.0f);          // x^2-1, cancellation-free near 1
    float xh = 0.5f * t;
    float r = __int_as_float(0x5f375a86 - (__float_as_int(t) >> 1));
    r = r * (1.5f - xh * r * r);
    r = r * (1.5f - xh * r * r);
    r = r * (1.5f - xh * r * r);
    float s = t * r;                             // sqrt(t)
    float c = x - s;
    return fminf(fmaxf(c, 0.0f), 1.0f);
}

#define BM 64
#define BN 64
#define BK 32

// Build C[b,n,m]: tiled "Lorentz GEMM" (component 0 of A negated), FFMA2 mainloop.
__global__ void build_coupling_kernel(const float* __restrict__ emb) {
    int b  = blockIdx.z;
    int n0 = blockIdx.y * BM;
    int m0 = blockIdx.x * BN;
    const float* E = emb + (size_t)b * NN * DD;

    __shared__ __align__(16) float As[BK][BM];
    __shared__ __align__(16) float Bs[BK][BN];

    int tx = threadIdx.x, ty = threadIdx.y;          // block (16,16)
    int tid = ty * 16 + tx;
    int loadRow = tid >> 3;                          // 0..31
    int loadK   = (tid & 7) * 4;                     // 0,4,...,28

    // acc[i][p]: row i, column-pair p -> (c[i][2p], c[i][2p+1]) packed f32x2
    unsigned long long acc[4][2] = {};

    for (int k0 = 0; k0 < DD; k0 += BK) {
        #pragma unroll
        for (int rr = 0; rr < 2; rr++) {
            int row = loadRow + rr * 32;
            float4 v = *(const float4*)(E + (size_t)(n0 + row) * DD + k0 + loadK);
            if (k0 == 0 && loadK == 0) v.x = -v.x;   // negate time component on A side
            As[loadK + 0][row] = v.x;
            As[loadK + 1][row] = v.y;
            As[loadK + 2][row] = v.z;
            As[loadK + 3][row] = v.w;
            float4 w = *(const float4*)(E + (size_t)(m0 + row) * DD + k0 + loadK);
            Bs[loadK + 0][row] = w.x;
            Bs[loadK + 1][row] = w.y;
            Bs[loadK + 2][row] = w.z;
            Bs[loadK + 3][row] = w.w;
        }
        __syncthreads();

        #pragma unroll
        for (int kk = 0; kk < BK; kk++) {
            float4 a4 = *(const float4*)&As[kk][ty * 4];
            ulonglong2 b2 = *(const ulonglong2*)&Bs[kk][tx * 4]; // (b0,b1),(b2,b3)
            unsigned long long a0 = pack2(a4.x, a4.x);
            unsigned long long a1 = pack2(a4.y, a4.y);
            unsigned long long a2 = pack2(a4.z, a4.z);
            unsigned long long a3 = pack2(a4.w, a4.w);
            fma2(acc[0][0], a0, b2.x); fma2(acc[0][1], a0, b2.y);
            fma2(acc[1][0], a1, b2.x); fma2(acc[1][1], a1, b2.y);
            fma2(acc[2][0], a2, b2.x); fma2(acc[2][1], a2, b2.y);
            fma2(acc[3][0], a3, b2.x); fma2(acc[3][1], a3, b2.y);
        }
        __syncthreads();
    }

    // Epilogue: lorentz -> coupling -> fp16, vectorized 8B store
    #pragma unroll
    for (int i = 0; i < 4; i++) {
        int n = n0 + ty * 4 + i;
        float c0, c1, c2, c3;
        unpack2(acc[i][0], c0, c1);
        unpack2(acc[i][1], c2, c3);
        c0 = coupling_from_lz(c0);
        c1 = coupling_from_lz(c1);
        c2 = coupling_from_lz(c2);
        c3 = coupling_from_lz(c3);
        __half2 h01 = __floats2half2_rn(c0, c1);
        __half2 h23 = __floats2half2_rn(c2, c3);
        uint2 o;
        o.x = *reinterpret_cast<unsigned*>(&h01);
        o.y = *reinterpret_cast<unsigned*>(&h23);
        *reinterpret_cast<uint2*>(d_C + ((size_t)b * NN + n) * NN + m0 + tx * 4) = o;
    }
}

// One Kuramoto step. Block = 256 threads (8 warps); each warp owns 4 C-rows
// (amortizes shared trig LDS 4x). sin(th_n - th_m) decomposed:
//   csum = sin_n * (C . cos) - cos_n * (C . sin), both matvecs via FFMA2.
__global__ void step_kernel(const float* __restrict__ src,
                            float* __restrict__ dst,
                            const float* __restrict__ omega) {
    __shared__ __align__(16) float cs[NN];
    __shared__ __align__(16) float sn[NN];

    int b = blockIdx.y;
    const float* th_b = src + b * NN;

    for (int i = threadIdx.x; i < NN; i += blockDim.x) {
        float s, c;
        sincosf(th_b[i], &s, &c);
        cs[i] = c;
        sn[i] = s;
    }
    __syncthreads();

    int wid  = threadIdx.x >> 5;
    int lane = threadIdx.x & 31;
    int row0 = blockIdx.x * 32 + wid * 4;

    const __half* Cb = d_C + ((size_t)b * NN + row0) * NN;

    unsigned long long accC[4] = {0, 0, 0, 0};
    unsigned long long accS[4] = {0, 0, 0, 0};

    #pragma unroll
    for (int it = 0; it < NN / 256; it++) {          // 8 iterations
        int j = it * 256 + lane * 8;
        // trig pairs straight out of shared (already adjacent-packed as u64)
        ulonglong2 cp = *(const ulonglong2*)&cs[j];      // (c0,c1),(c2,c3)
        ulonglong2 cq = *(const ulonglong2*)&cs[j + 4];  // (c4,c5),(c6,c7)
        ulonglong2 sp = *(const ulonglong2*)&sn[j];
        ulonglong2 sq = *(const ulonglong2*)&sn[j + 4];
        #pragma unroll
        for (int r = 0; r < 4; r++) {
            uint4 v = *(const uint4*)(Cb + (size_t)r * NN + j);  // 8 halves
            __half2 h0 = *reinterpret_cast<__half2*>(&v.x);
            __half2 h1 = *reinterpret_cast<__half2*>(&v.y);
            __half2 h2 = *reinterpret_cast<__half2*>(&v.z);
            __half2 h3 = *reinterpret_cast<__half2*>(&v.w);
            float2 f0 = __half22float2(h0);
            float2 f1 = __half22float2(h1);
            float2 f2 = __half22float2(h2);
            float2 f3 = __half22float2(h3);
            unsigned long long C01 = pack2(f0.x, f0.y);
            unsigned long long C23 = pack2(f1.x, f1.y);
            unsigned long long C45 = pack2(f2.x, f2.y);
            unsigned long long C67 = pack2(f3.x, f3.y);
            fma2(accC[r], C01, cp.x); fma2(accC[r], C23, cp.y);
            fma2(accC[r], C45, cq.x); fma2(accC[r], C67, cq.y);
            fma2(accS[r], C01, sp.x); fma2(accS[r], C23, sp.y);
            fma2(accS[r], C45, sq.x); fma2(accS[r], C67, sq.y);
        }
    }

    #pragma unroll
    for (int r = 0; r < 4; r++) {
        float c0, c1, s0, s1;
        unpack2(accC[r], c0, c1);
        unpack2(accS[r], s0, s1);
        float sum_c = c0 + c1;
        float sum_s = s0 + s1;
        #pragma unroll
        for (int off = 16; off > 0; off >>= 1) {
            sum_c += __shfl_xor_sync(0xFFFFFFFFu, sum_c, off);
            sum_s += __shfl_xor_sync(0xFFFFFFFFu, sum_s, off);
        }
        if (lane == 0) {
            int n = row0 + r;
            float th = th_b[n];
            float csum = sn[n] * sum_c - cs[n] * sum_s;
            float dth = omega[n] + (1.0f / NN) * csum;   // K_STRENGTH/N
            dst[b * NN + n] = fmodf(th + 0.1f * dth, TWO_PI_F);
        }
    }
}

extern "C" void kernel_launch(void* const* d_in, const int* in_sizes, int n_in,
                              void* d_out, int out_size) {
    const float* initial = (const float*)d_in[0];   // (B,N)
    const float* emb     = (const float*)d_in[1];   // (B,N,D)
    const float* omega   = (const float*)d_in[2];   // (N,)
    float* out = (float*)d_out;                     // (B,N)

    float* buf = nullptr;
    cudaGetSymbolAddress((void**)&buf, d_theta_buf);

    dim3 bgrid(NN / BN, NN / BM, BB);
    dim3 bblock(16, 16);
    build_coupling_kernel<<<bgrid, bblock>>>(emb);

    dim3 sgrid(NN / 32, BB);
    for (int k = 0; k < 16; k++) {
        const float* src = (k == 0)  ? initial : buf + ((k + 1) & 1) * BB * NN;
        float*       dst = (k == 15) ? out     : buf + (k & 1) * BB * NN;
        step_kernel<<<sgrid, 256>>>(src, dst, omega);
    }
}

// round 3
// speedup vs baseline: 1.9708x; 1.2945x over previous
#include <cuda_runtime.h>
#include <cuda_fp16.h>
#include <math.h>

#define BB 8
#define NN 2048
#define DD 128
#define G  16                       // NN / 128 column groups
#define TWO_PI_F 6.283185307179586f

// Static device scratch (no allocations allowed).
__device__ __half d_C[(size_t)BB * NN * NN];      // 67 MB; only upper-triangle 128-tiles valid
__device__ float d_theta_buf[2 * BB * NN];        // ping-pong theta
__device__ float d_trigC[BB * NN];                // cos(theta) current
__device__ float d_trigS[BB * NN];                // sin(theta) current
__device__ float d_partC[BB * G * G * 128];      // y_c partials  [b][g][slot][128]
__device__ float d_partS[BB * G * G * 128];      // y_s partials

// ---- packed f32x2 helpers (Blackwell FFMA2) ----
static __device__ __forceinline__ unsigned long long pack2(float lo, float hi) {
    unsigned long long r;
    asm("mov.b64 %0, {%1, %2};" : "=l"(r) : "f"(lo), "f"(hi));
    return r;
}
static __device__ __forceinline__ void unpack2(unsigned long long v, float& lo, float& hi) {
    asm("mov.b64 {%0, %1}, %2;" : "=f"(lo), "=f"(hi) : "l"(v));
}
static __device__ __forceinline__ void fma2(unsigned long long& d,
                                            unsigned long long a,
                                            unsigned long long b) {
    asm("fma.rn.f32x2 %0, %1, %2, %0;" : "+l"(d) : "l"(a), "l"(b));
}

// coupling = clip(exp(-acosh(max(-lz,1+1e-7))/(1+1e-6)),0,1) ≈ x - sqrt(x^2-1)
// sqrt via FMA-pipe Newton (avoids MUFU rt=8 bottleneck for 33.5M elements)
__device__ __forceinline__ float coupling_from_lz(float lz) {
    float x = fmaxf(-lz, 1.0f + 1e-7f);
    float t = (x - 1.0f) * (x + 1.0f);
    float xh = 0.5f * t;
    float r = __int_as_float(0x5f375a86 - (__float_as_int(t) >> 1));
    r = r * (1.5f - xh * r * r);
    r = r * (1.5f - xh * r * r);
    r = r * (1.5f - xh * r * r);
    float s = t * r;
    float c = x - s;
    return fminf(fmaxf(c, 0.0f), 1.0f);
}

#define BM 64
#define BN 64
#define BK 32

// Build C[b,n,m] for upper-triangle 128-tiles only (C is symmetric).
__global__ void build_coupling_kernel(const float* __restrict__ emb) {
    // keep only 128-tiles with m128 >= n128
    int m128 = blockIdx.x >> 1;
    int n128 = blockIdx.y >> 1;
    if (m128 < n128) return;

    int b  = blockIdx.z;
    int n0 = blockIdx.y * BM;
    int m0 = blockIdx.x * BN;
    const float* E = emb + (size_t)b * NN * DD;

    __shared__ __align__(16) float As[BK][BM];
    __shared__ __align__(16) float Bs[BK][BN];

    int tx = threadIdx.x, ty = threadIdx.y;          // block (16,16)
    int tid = ty * 16 + tx;
    int loadRow = tid >> 3;
    int loadK   = (tid & 7) * 4;

    unsigned long long acc[4][2] = {};

    for (int k0 = 0; k0 < DD; k0 += BK) {
        #pragma unroll
        for (int rr = 0; rr < 2; rr++) {
            int row = loadRow + rr * 32;
            float4 v = *(const float4*)(E + (size_t)(n0 + row) * DD + k0 + loadK);
            if (k0 == 0 && loadK == 0) v.x = -v.x;
            As[loadK + 0][row] = v.x;
            As[loadK + 1][row] = v.y;
            As[loadK + 2][row] = v.z;
            As[loadK + 3][row] = v.w;
            float4 w = *(const float4*)(E + (size_t)(m0 + row) * DD + k0 + loadK);
            Bs[loadK + 0][row] = w.x;
            Bs[loadK + 1][row] = w.y;
            Bs[loadK + 2][row] = w.z;
            Bs[loadK + 3][row] = w.w;
        }
        __syncthreads();

        #pragma unroll
        for (int kk = 0; kk < BK; kk++) {
            float4 a4 = *(const float4*)&As[kk][ty * 4];
            ulonglong2 b2 = *(const ulonglong2*)&Bs[kk][tx * 4];
            unsigned long long a0 = pack2(a4.x, a4.x);
            unsigned long long a1 = pack2(a4.y, a4.y);
            unsigned long long a2 = pack2(a4.z, a4.z);
            unsigned long long a3 = pack2(a4.w, a4.w);
            fma2(acc[0][0], a0, b2.x); fma2(acc[0][1], a0, b2.y);
            fma2(acc[1][0], a1, b2.x); fma2(acc[1][1], a1, b2.y);
            fma2(acc[2][0], a2, b2.x); fma2(acc[2][1], a2, b2.y);
            fma2(acc[3][0], a3, b2.x); fma2(acc[3][1], a3, b2.y);
        }
        __syncthreads();
    }

    #pragma unroll
    for (int i = 0; i < 4; i++) {
        int n = n0 + ty * 4 + i;
        float c0, c1, c2, c3;
        unpack2(acc[i][0], c0, c1);
        unpack2(acc[i][1], c2, c3);
        c0 = coupling_from_lz(c0);
        c1 = coupling_from_lz(c1);
        c2 = coupling_from_lz(c2);
        c3 = coupling_from_lz(c3);
        __half2 h01 = __floats2half2_rn(c0, c1);
        __half2 h23 = __floats2half2_rn(c2, c3);
        uint2 o;
        o.x = *reinterpret_cast<unsigned*>(&h01);
        o.y = *reinterpret_cast<unsigned*>(&h23);
        *reinterpret_cast<uint2*>(d_C + ((size_t)b * NN + n) * NN + m0 + tx * 4) = o;
    }
}

// Init: trig tables from initial theta.
__global__ void init_trig_kernel(const float* __restrict__ th) {
    int i = blockIdx.x * 256 + threadIdx.x;      // i < BB*NN
    float s, c;
    sincosf(th[i], &s, &c);
    d_trigC[i] = c;
    d_trigS[i] = s;
}

// Tile kernel: one block per upper-triangle 128x128 tile (I,J).
// Computes rowparts (group I) from C*trig[J-range]; for J>I also colparts
// (group J) from C^T * trig[I-range] using the SAME loaded data.
__global__ void tile_kernel() {
    int b = blockIdx.y;
    int t = blockIdx.x, I = 0;
    while (t >= G - I) { t -= G - I; I++; }
    int J = I + t;
    bool offdiag = (J != I);

    int tid  = threadIdx.x;                       // 256 threads, 8 warps
    int w    = tid >> 5;
    int lane = tid & 31;

    __shared__ __align__(16) float shCI[128], shSI[128];
    __shared__ __align__(16) float shColC[8][128];
    __shared__ __align__(16) float shColS[8][128];

    const float* cosB = d_trigC + b * NN;
    const float* sinB = d_trigS + b * NN;
    if (tid < 128) {
        shCI[tid] = cosB[I * 128 + tid];
        shSI[tid] = sinB[I * 128 + tid];
    }
    int c0 = lane * 4;
    float4 cj = *(const float4*)(cosB + J * 128 + c0);
    float4 sj = *(const float4*)(sinB + J * 128 + c0);
    unsigned long long cj01 = pack2(cj.x, cj.y), cj23 = pack2(cj.z, cj.w);
    unsigned long long sj01 = pack2(sj.x, sj.y), sj23 = pack2(sj.z, sj.w);
    __syncthreads();

    const __half* Ct = d_C + ((size_t)b * NN + I * 128 + w * 16) * NN + J * 128;

    unsigned long long colC01 = 0, colC23 = 0, colS01 = 0, colS23 = 0;
    float resC = 0.0f, resS = 0.0f;   // this lane's own-row results (lane<16)

    #pragma unroll
    for (int r = 0; r < 16; r++) {
        uint2 v = *(const uint2*)(Ct + (size_t)r * NN + c0);
        __half2 h0 = *reinterpret_cast<__half2*>(&v.x);
        __half2 h1 = *reinterpret_cast<__half2*>(&v.y);
        float2 f0 = __half22float2(h0);
        float2 f1 = __half22float2(h1);
        unsigned long long C01 = pack2(f0.x, f0.y);
        unsigned long long C23 = pack2(f1.x, f1.y);

        // row partials (dot with col trig)
        unsigned long long rc = 0, rs = 0;
        fma2(rc, C01, cj01); fma2(rc, C23, cj23);
        fma2(rs, C01, sj01); fma2(rs, C23, sj23);
        float rcl, rch, rsl, rsh;
        unpack2(rc, rcl, rch);
        unpack2(rs, rsl, rsh);
        float rowc = rcl + rch;
        float rows_ = rsl + rsh;
        #pragma unroll
        for (int off = 16; off > 0; off >>= 1) {
            rowc  += __shfl_xor_sync(0xFFFFFFFFu, rowc,  off);
            rows_ += __shfl_xor_sync(0xFFFFFFFFu, rows_, off);
        }
        if (lane == r) { resC = rowc; resS = rows_; }

        // column partials (transpose use), off-diagonal tiles only
        if (offdiag) {
            float ci = shCI[w * 16 + r], si = shSI[w * 16 + r];
            unsigned long long cis = pack2(ci, ci);
            unsigned long long sis = pack2(si, si);
            fma2(colC01, C01, cis); fma2(colC23, C23, cis);
            fma2(colS01, C01, sis); fma2(colS23, C23, sis);
        }
    }

    // write rowparts: slot [b][I][J], coalesced over 16 lanes
    if (lane < 16) {
        size_t base = (((size_t)b * G + I) * G + J) * 128 + w * 16 + lane;
        d_partC[base] = resC;
        d_partS[base] = resS;
    }

    if (offdiag) {
        // reduce col partials across warps via shared
        float x0, x1, x2, x3;
        unpack2(colC01, x0, x1); unpack2(colC23, x2, x3);
        *(float4*)&shColC[w][c0] = make_float4(x0, x1, x2, x3);
        unpack2(colS01, x0, x1); unpack2(colS23, x2, x3);
        *(float4*)&shColS[w][c0] = make_float4(x0, x1, x2, x3);
        __syncthreads();

        int c = tid & 127;
        float acc = 0.0f;
        if (tid < 128) {
            #pragma unroll
            for (int ww = 0; ww < 8; ww++) acc += shColC[ww][c];
            d_partC[(((size_t)b * G + J) * G + I) * 128 + c] = acc;
        } else {
            #pragma unroll
            for (int ww = 0; ww < 8; ww++) acc += shColS[ww][c];
            d_partS[(((size_t)b * G + J) * G + I) * 128 + c] = acc;
        }
    }
}

// Finalize: sum 16 slots, theta update, write new trig tables.
__global__ void finalize_kernel(const float* __restrict__ th_in,
                                float* __restrict__ th_out,
                                const float* __restrict__ omega) {
    int b = blockIdx.y;
    int n = blockIdx.x * 256 + threadIdx.x;
    int g = n >> 7, c = n & 127;

    float yc = 0.0f, ys = 0.0f;
    size_t base = (((size_t)b * G + g) * G) * 128 + c;
    #pragma unroll
    for (int k = 0; k < G; k++) {
        yc += d_partC[base + (size_t)k * 128];
        ys += d_partS[base + (size_t)k * 128];
    }

    int gi = b * NN + n;
    float sn = d_trigS[gi], cn = d_trigC[gi];
    float csum = sn * yc - cn * ys;
    float dth = omega[n] + (1.0f / NN) * csum;
    float thn = fmodf(th_in[gi] + 0.1f * dth, TWO_PI_F);
    th_out[gi] = thn;

    float s, cc;
    sincosf(thn, &s, &cc);
    d_trigC[gi] = cc;
    d_trigS[gi] = s;
}

extern "C" void kernel_launch(void* const* d_in, const int* in_sizes, int n_in,
                              void* d_out, int out_size) {
    const float* initial = (const float*)d_in[0];   // (B,N)
    const float* emb     = (const float*)d_in[1];   // (B,N,D)
    const float* omega   = (const float*)d_in[2];   // (N,)
    float* out = (float*)d_out;                     // (B,N)

    float* buf = nullptr;
    cudaGetSymbolAddress((void**)&buf, d_theta_buf);

    dim3 bgrid(NN / BN, NN / BM, BB);
    dim3 bblock(16, 16);
    build_coupling_kernel<<<bgrid, bblock>>>(emb);
    init_trig_kernel<<<BB * NN / 256, 256>>>(initial);

    dim3 tgrid(G * (G + 1) / 2, BB);   // 136 upper-triangle tiles x 8 batches
    dim3 fgrid(NN / 256, BB);
    for (int k = 0; k < 16; k++) {
        const float* src = (k == 0)  ? initial : buf + ((k + 1) & 1) * BB * NN;
        float*       dst = (k == 15) ? out     : buf + (k & 1) * BB * NN;
        tile_kernel<<<tgrid, 256>>>();
        finalize_kernel<<<fgrid, 256>>>(src, dst, omega);
    }
}

// round 4
// speedup vs baseline: 2.4520x; 1.2442x over previous
#include <cuda_runtime.h>
#include <cuda_fp16.h>
#include <cuda_fp8.h>
#include <math.h>

#define BB 8
#define NN 2048
#define DD 128
#define G  16
#define TWO_PI_F 6.283185307179586f

// Static device scratch (no allocations allowed).
__device__ unsigned char d_C8[(size_t)BB * NN * NN];  // 33.5 MB full coupling, e4m3
__device__ float d_theta_buf[2 * BB * NN];            // ping-pong theta
__device__ float d_trigC[BB * NN];                    // cos(theta)
__device__ float d_trigS[BB * NN];                    // sin(theta)

// ---- packed f32x2 helpers (Blackwell FFMA2) ----
static __device__ __forceinline__ unsigned long long pack2(float lo, float hi) {
    unsigned long long r;
    asm("mov.b64 %0, {%1, %2};" : "=l"(r) : "f"(lo), "f"(hi));
    return r;
}
static __device__ __forceinline__ void unpack2(unsigned long long v, float& lo, float& hi) {
    asm("mov.b64 {%0, %1}, %2;" : "=f"(lo), "=f"(hi) : "l"(v));
}
static __device__ __forceinline__ void fma2(unsigned long long& d,
                                            unsigned long long a,
                                            unsigned long long b) {
    asm("fma.rn.f32x2 %0, %1, %2, %0;" : "+l"(d) : "l"(a), "l"(b));
}

// coupling ≈ x - sqrt(x^2-1), x = max(-lz, 1+1e-7)  (exact up to factor exp(1e-6 d) ≤ 1+5e-6)
__device__ __forceinline__ float coupling_from_lz(float lz) {
    float x = fmaxf(-lz, 1.0f + 1e-7f);
    float t = (x - 1.0f) * (x + 1.0f);
    float xh = 0.5f * t;
    float r = __int_as_float(0x5f375a86 - (__float_as_int(t) >> 1));
    r = r * (1.5f - xh * r * r);
    r = r * (1.5f - xh * r * r);
    r = r * (1.5f - xh * r * r);
    float s = t * r;
    float c = x - s;
    return fminf(fmaxf(c, 0.0f), 1.0f);
}

static __device__ __forceinline__ unsigned fp8x4_from_floats(float c0, float c1,
                                                             float c2, float c3) {
    __nv_fp8x2_storage_t p01 =
        __nv_cvt_float2_to_fp8x2(make_float2(c0, c1), __NV_SATFINITE, __NV_E4M3);
    __nv_fp8x2_storage_t p23 =
        __nv_cvt_float2_to_fp8x2(make_float2(c2, c3), __NV_SATFINITE, __NV_E4M3);
    return (unsigned)p01 | ((unsigned)p23 << 16);
}

#define BM 64
#define BN 64
#define BK 32

// Build C for upper-triangle 128-tiles; strictly-upper blocks also write the
// transposed mirror (so step kernels see a FULL symmetric fp8 matrix).
__global__ void build_coupling_kernel(const float* __restrict__ emb) {
    int m128 = blockIdx.x >> 1;
    int n128 = blockIdx.y >> 1;
    if (m128 < n128) return;
    bool twrite = (m128 > n128);

    int b  = blockIdx.z;
    int n0 = blockIdx.y * BM;
    int m0 = blockIdx.x * BN;
    const float* E = emb + (size_t)b * NN * DD;

    __shared__ __align__(16) float As[BK][BM];
    __shared__ __align__(16) float Bs[BK][BN];
    __shared__ unsigned shT[64 * 17];          // 64x64 fp8 stage, 17-word rows

    int tx = threadIdx.x, ty = threadIdx.y;    // block (16,16)
    int tid = ty * 16 + tx;
    int loadRow = tid >> 3;
    int loadK   = (tid & 7) * 4;

    unsigned long long acc[4][2] = {};

    for (int k0 = 0; k0 < DD; k0 += BK) {
        #pragma unroll
        for (int rr = 0; rr < 2; rr++) {
            int row = loadRow + rr * 32;
            float4 v = *(const float4*)(E + (size_t)(n0 + row) * DD + k0 + loadK);
            if (k0 == 0 && loadK == 0) v.x = -v.x;
            As[loadK + 0][row] = v.x;
            As[loadK + 1][row] = v.y;
            As[loadK + 2][row] = v.z;
            As[loadK + 3][row] = v.w;
            float4 w = *(const float4*)(E + (size_t)(m0 + row) * DD + k0 + loadK);
            Bs[loadK + 0][row] = w.x;
            Bs[loadK + 1][row] = w.y;
            Bs[loadK + 2][row] = w.z;
            Bs[loadK + 3][row] = w.w;
        }
        __syncthreads();

        #pragma unroll
        for (int kk = 0; kk < BK; kk++) {
            float4 a4 = *(const float4*)&As[kk][ty * 4];
            ulonglong2 b2 = *(const ulonglong2*)&Bs[kk][tx * 4];
            unsigned long long a0 = pack2(a4.x, a4.x);
            unsigned long long a1 = pack2(a4.y, a4.y);
            unsigned long long a2 = pack2(a4.z, a4.z);
            unsigned long long a3 = pack2(a4.w, a4.w);
            fma2(acc[0][0], a0, b2.x); fma2(acc[0][1], a0, b2.y);
            fma2(acc[1][0], a1, b2.x); fma2(acc[1][1], a1, b2.y);
            fma2(acc[2][0], a2, b2.x); fma2(acc[2][1], a2, b2.y);
            fma2(acc[3][0], a3, b2.x); fma2(acc[3][1], a3, b2.y);
        }
        __syncthreads();
    }

    // Epilogue: coupling -> fp8, store upper block (+stage for transpose)
    #pragma unroll
    for (int i = 0; i < 4; i++) {
        int n = n0 + ty * 4 + i;
        float c0, c1, c2, c3;
        unpack2(acc[i][0], c0, c1);
        unpack2(acc[i][1], c2, c3);
        c0 = coupling_from_lz(c0);
        c1 = coupling_from_lz(c1);
        c2 = coupling_from_lz(c2);
        c3 = coupling_from_lz(c3);
        unsigned o = fp8x4_from_floats(c0, c1, c2, c3);
        *(unsigned*)(d_C8 + ((size_t)b * NN + n) * NN + m0 + tx * 4) = o;
        if (twrite) shT[(ty * 4 + i) * 17 + tx] = o;   // row = local n, word = col quad
    }

    if (twrite) {
        __syncthreads();
        // write transposed block at (rows m0.., cols n0..): out[mm][nn] = in[nn][mm]
        #pragma unroll
        for (int k = 0; k < 4; k++) {
            int idx = k * 256 + tid;           // 1024 output uints
            int mm = idx >> 4;                 // 0..63 output row (local col of input)
            int qn = idx & 15;                 // output col quad (local row of input /4)
            int word = mm >> 2, sh = (mm & 3) * 8;
            unsigned u0 = shT[(qn * 4 + 0) * 17 + word];
            unsigned u1 = shT[(qn * 4 + 1) * 17 + word];
            unsigned u2 = shT[(qn * 4 + 2) * 17 + word];
            unsigned u3 = shT[(qn * 4 + 3) * 17 + word];
            unsigned o = ((u0 >> sh) & 0xFFu)
                       | (((u1 >> sh) & 0xFFu) << 8)
                       | (((u2 >> sh) & 0xFFu) << 16)
                       | (((u3 >> sh) & 0xFFu) << 24);
            *(unsigned*)(d_C8 + ((size_t)b * NN + m0 + mm) * NN + n0 + qn * 4) = o;
        }
    }
}

__global__ void init_trig_kernel(const float* __restrict__ th) {
    int i = blockIdx.x * 256 + threadIdx.x;
    float s, c;
    sincosf(th[i], &s, &c);
    d_trigC[i] = c;
    d_trigS[i] = s;
}

// Fused step: block (g, b) computes y_c/y_s for its 128 output columns via
// pure column-pattern over ALL 2048 rows (full symmetric C), then does the
// theta update + next-step trig in the tail. No partials, no finalize.
__global__ void __launch_bounds__(512, 1)
step_kernel(const float* __restrict__ th_in,
            float* __restrict__ th_out,
            const float* __restrict__ omega) {
    __shared__ __align__(16) float shC[NN];
    __shared__ __align__(16) float shS[NN];
    __shared__ __align__(16) float shRedC[32 * 132];
    __shared__ __align__(16) float shRedS[32 * 132];
    __shared__ float shYc[128], shYs[128];

    int g = blockIdx.x, b = blockIdx.y;
    int tid = threadIdx.x;
    int w = tid >> 5, lane = tid & 31;

    // stage full trig vectors for this batch
    {
        const float4* c4 = (const float4*)(d_trigC + b * NN);
        const float4* s4 = (const float4*)(d_trigS + b * NN);
        ((float4*)shC)[tid] = c4[tid];
        ((float4*)shS)[tid] = s4[tid];
    }
    __syncthreads();

    int h = lane >> 4;                 // row parity within pass
    int co = (lane & 15) * 8;          // this lane's 8 columns
    const unsigned char* Cb = d_C8 + ((size_t)b * NN + w * 128) * NN + g * 128 + co;

    unsigned long long accC[4] = {0, 0, 0, 0};
    unsigned long long accS[4] = {0, 0, 0, 0};

    #pragma unroll 4
    for (int p = 0; p < 64; p++) {     // warp covers rows w*128 + 2p + h
        int n = w * 128 + 2 * p + h;
        uint2 v = *(const uint2*)(Cb + ((size_t)(2 * p + h)) * NN);

        __half2 h0 = __half2(__nv_cvt_fp8x2_to_halfraw2((__nv_fp8x2_storage_t)(v.x & 0xFFFF), __NV_E4M3));
        __half2 h1 = __half2(__nv_cvt_fp8x2_to_halfraw2((__nv_fp8x2_storage_t)(v.x >> 16),    __NV_E4M3));
        __half2 h2 = __half2(__nv_cvt_fp8x2_to_halfraw2((__nv_fp8x2_storage_t)(v.y & 0xFFFF), __NV_E4M3));
        __half2 h3 = __half2(__nv_cvt_fp8x2_to_halfraw2((__nv_fp8x2_storage_t)(v.y >> 16),    __NV_E4M3));
        float2 f0 = __half22float2(h0);
        float2 f1 = __half22float2(h1);
        float2 f2 = __half22float2(h2);
        float2 f3 = __half22float2(h3);
        unsigned long long C0 = pack2(f0.x, f0.y);
        unsigned long long C1 = pack2(f1.x, f1.y);
        unsigned long long C2 = pack2(f2.x, f2.y);
        unsigned long long C3 = pack2(f3.x, f3.y);

        float cn = shC[n], sn = shS[n];
        unsigned long long cnn = pack2(cn, cn);
        unsigned long long snn = pack2(sn, sn);
        fma2(accC[0], C0, cnn); fma2(accC[1], C1, cnn);
        fma2(accC[2], C2, cnn); fma2(accC[3], C3, cnn);
        fma2(accS[0], C0, snn); fma2(accS[1], C1, snn);
        fma2(accS[2], C2, snn); fma2(accS[3], C3, snn);
    }

    // stash per-(warp,half) column partials
    {
        int slot = w * 2 + h;
        float* pc = &shRedC[slot * 132 + co];
        float* ps = &shRedS[slot * 132 + co];
        float x0, x1, x2, x3;
        unpack2(accC[0], x0, x1); unpack2(accC[1], x2, x3);
        *(float4*)pc = make_float4(x0, x1, x2, x3);
        unpack2(accC[2], x0, x1); unpack2(accC[3], x2, x3);
        *(float4*)(pc + 4) = make_float4(x0, x1, x2, x3);
        unpack2(accS[0], x0, x1); unpack2(accS[1], x2, x3);
        *(float4*)ps = make_float4(x0, x1, x2, x3);
        unpack2(accS[2], x0, x1); unpack2(accS[3], x2, x3);
        *(float4*)(ps + 4) = make_float4(x0, x1, x2, x3);
    }
    __syncthreads();

    // reduce 32 slots -> yc/ys
    if (tid < 256) {
        int col = tid & 127;
        const float* base = (tid < 128) ? shRedC : shRedS;
        float acc = 0.0f;
        #pragma unroll
        for (int s = 0; s < 32; s++) acc += base[s * 132 + col];
        if (tid < 128) shYc[col] = acc; else shYs[col] = acc;
    }
    __syncthreads();

    // theta update + trig for next step
    if (tid < 128) {
        int n = g * 128 + tid;
        int gi = b * NN + n;
        float sn = shS[n], cn = shC[n];
        float csum = sn * shYc[tid] - cn * shYs[tid];
        float dth = omega[n] + (1.0f / NN) * csum;
        float thn = fmodf(th_in[gi] + 0.1f * dth, TWO_PI_F);
        th_out[gi] = thn;
        float s2, c2;
        sincosf(thn, &s2, &c2);
        d_trigC[gi] = c2;
        d_trigS[gi] = s2;
    }
}

extern "C" void kernel_launch(void* const* d_in, const int* in_sizes, int n_in,
                              void* d_out, int out_size) {
    const float* initial = (const float*)d_in[0];   // (B,N)
    const float* emb     = (const float*)d_in[1];   // (B,N,D)
    const float* omega   = (const float*)d_in[2];   // (N,)
    float* out = (float*)d_out;                     // (B,N)

    float* buf = nullptr;
    cudaGetSymbolAddress((void**)&buf, d_theta_buf);

    dim3 bgrid(NN / BN, NN / BM, BB);
    dim3 bblock(16, 16);
    build_coupling_kernel<<<bgrid, bblock>>>(emb);
    init_trig_kernel<<<BB * NN / 256, 256>>>(initial);

    dim3 sgrid(G, BB);
    for (int k = 0; k < 16; k++) {
        const float* src = (k == 0)  ? initial : buf + ((k + 1) & 1) * BB * NN;
        float*       dst = (k == 15) ? out     : buf + (k & 1) * BB * NN;
        step_kernel<<<sgrid, 512>>>(src, dst, omega);
    }
}